// round 6
// baseline (speedup 1.0000x reference)
#include <cuda_runtime.h>
#include <cuda_bf16.h>
#include <cstdint>
#include <cstddef>

#define BB 64
#define TT 2048
#define DD 256
#define VV 256
#define QNAN_U 0x7fc00000u

// ---------------- device scratch (no cudaMalloc allowed) ----------------
__device__ __align__(16) float g_EWx[VV * DD];            // E @ Wx_w^T   [v][e]
__device__ __align__(16) float g_G[VV * DD];              // sigmoid(E @ Wz_w^T) [v][e]
__device__ __align__(16) float g_y[(size_t)BB * TT * DD]; // gated hidden states [b,t,e]

// ---------------- helpers ----------------
__device__ __forceinline__ uint32_t smem_u32(const void* p) {
    uint32_t a;
    asm("{ .reg .u64 t; cvta.to.shared.u64 t, %1; cvt.u32.u64 %0, t; }"
        : "=r"(a) : "l"(p));
    return a;
}

// packed fp32x2 FMA: acc = a*b + acc  (full fp32 precision, 2 MACs / instr)
#define FFMA2(acc, a, b) \
    asm("fma.rn.f32x2 %0, %1, %2, %0;" : "+l"(acc) : "l"(a), "l"(b))

__device__ __forceinline__ float f32x2_hsum4(unsigned long long a,
                                             unsigned long long b) {
    unsigned long long s;
    asm("add.rn.f32x2 %0, %1, %2;" : "=l"(s) : "l"(a), "l"(b));
    float lo, hi;
    asm("mov.b64 {%0, %1}, %2;" : "=f"(lo), "=f"(hi) : "l"(s));
    return lo + hi;
}

// fast tanh: 1 - 2/(exp(2x)+1); exact limits at +-inf, ~1e-6 rel err, never NaN
__device__ __forceinline__ float tanh_fast(float x) {
    float e = __expf(2.0f * x);
    return 1.0f - __fdividef(2.0f, e + 1.0f);
}

// ================= Kernel 1: tiny projection tables =================
__global__ __launch_bounds__(256) void proj_kernel(
    const float* __restrict__ E,
    const float* __restrict__ Wx,
    const float* __restrict__ Wz)
{
    __shared__ __align__(16) float4 er[DD / 4];
    const int v = blockIdx.x;
    const int e = threadIdx.x;
    if (e < DD / 4) er[e] = ((const float4*)(E + (size_t)v * DD))[e];
    __syncthreads();

    const float4* wx4 = (const float4*)(Wx + (size_t)e * DD);
    const float4* wz4 = (const float4*)(Wz + (size_t)e * DD);
    float ax0 = 0.f, ax1 = 0.f, az0 = 0.f, az1 = 0.f;
#pragma unroll 8
    for (int i = 0; i < DD / 4; i++) {
        float4 ev = er[i];
        float4 a = wx4[i];
        float4 b = wz4[i];
        ax0 += ev.x * a.x + ev.y * a.y;
        ax1 += ev.z * a.z + ev.w * a.w;
        az0 += ev.x * b.x + ev.y * b.y;
        az1 += ev.z * b.z + ev.w * b.w;
    }
    g_EWx[v * DD + e] = ax0 + ax1;
    g_G[v * DD + e]   = 1.f / (1.f + expf(-(az0 + az1)));
}

// ================= Kernel 2: recurrence =================
// 32 clusters of 2 CTAs; each cluster advances TWO batch chains in lockstep.
// CTA rank r computes outputs eg in [128r,128r+128) for BOTH chains.
//   eloc = tid>>2 (output), q = tid&3 (k-slice of 64: 32 local + 32 remote).
// Chain B's compute fills chain A's DSMEM publish->consume latency window
// (and vice versa), so polls succeed first-try and the step period is the
// FMA issue floor, not the fabric round-trip.
// Sync: data-as-flag (qNaN sentinels, weak st.shared::cluster publishes),
// 4-deep hrem ring, ONE __syncthreads per step (re-arm rides after it;
// peer's next write into a re-armed buffer is causally >= 2 steps later).
#define HP 140          // 3*36 + 32 (32-float chunks at stride 36 words)
#define HB (HP * 4)     // 560 bytes per buffer

__global__ void __cluster_dims__(2, 1, 1) __launch_bounds__(512, 1)
rnn_kernel(const int* __restrict__ tokens, const float* __restrict__ Wh)
{
    __shared__ int stok[2][TT];
    __shared__ __align__(16) float hloc[2][2][HP];   // [chain][parity]
    __shared__ __align__(16) float hrem[2][4][HP];   // [chain][t&3]

    const int tid  = threadIdx.x;
    const int bx   = blockIdx.x;
    const int cid  = bx >> 1;          // cluster id: chains 2cid, 2cid+1
    const int rank = bx & 1;
    const int q    = tid & 3;
    const int eloc = tid >> 2;
    const int eg   = rank * 128 + eloc;
    const int c0   = 2 * cid;

    // ---- weights: 16 f32x2 local-half + 16 f32x2 remote-half ----
    unsigned long long wL[16], wR[16];
    {
        const ulonglong2* sL = (const ulonglong2*)
            (Wh + (size_t)eg * DD + 128 * rank + 32 * q);
        const ulonglong2* sR = (const ulonglong2*)
            (Wh + (size_t)eg * DD + 128 * (rank ^ 1) + 32 * q);
#pragma unroll
        for (int j = 0; j < 8; j++) {
            ulonglong2 a = sL[j];
            wL[2 * j] = a.x; wL[2 * j + 1] = a.y;
            ulonglong2 c = sR[j];
            wR[2 * j] = c.x; wR[2 * j + 1] = c.y;
        }
    }

    for (int i = tid; i < TT; i += 512) {
        stok[0][i] = tokens[(size_t)c0 * TT + i];
        stok[1][i] = tokens[(size_t)(c0 + 1) * TT + i];
    }
    if (tid < HP) {
        hloc[0][0][tid] = 0.f; hloc[0][1][tid] = 0.f;    // h0 = 0
        hloc[1][0][tid] = 0.f; hloc[1][1][tid] = 0.f;
        hrem[0][0][tid] = 0.f; hrem[1][0][tid] = 0.f;    // step 0 reads zeros
#pragma unroll
        for (int bfr = 1; bfr < 4; bfr++) {
            ((unsigned int*)hrem[0][bfr])[tid] = QNAN_U;
            ((unsigned int*)hrem[1][bfr])[tid] = QNAN_U;
        }
    }

    // cluster barrier: all smem init visible before any peer traffic
    asm volatile("barrier.cluster.arrive.aligned;" ::: "memory");
    asm volatile("barrier.cluster.wait.aligned;"   ::: "memory");

    const int jp = eloc + ((eloc >> 5) << 2);      // padded produce index
    // peer publish bases (address of peer hrem[c][0][jp])
    uint32_t rpub[2];
    {
        const int peer = rank ^ 1;
        uint32_t l0 = smem_u32(&hrem[0][0][jp]);
        uint32_t l1 = smem_u32(&hrem[1][0][jp]);
        asm("mapa.shared::cluster.u32 %0, %1, %2;" : "=r"(rpub[0]) : "r"(l0), "r"(peer));
        asm("mapa.shared::cluster.u32 %0, %1, %2;" : "=r"(rpub[1]) : "r"(l1), "r"(peer));
    }
    // local poll bases (this thread's 32 remote-half words, buffer 0)
    uint32_t pbase[2];
    pbase[0] = smem_u32(&hrem[0][0][36 * q]);
    pbase[1] = smem_u32(&hrem[1][0][36 * q]);

    float* yb[2];
    yb[0] = g_y + (size_t)c0 * TT * DD;
    yb[1] = g_y + (size_t)(c0 + 1) * TT * DD;

    // prefetch step-0 gathers for both chains
    float wxn[2] = {0.f, 0.f}, ggn[2] = {0.f, 0.f};
    if (q == 0) {
#pragma unroll
        for (int c = 0; c < 2; c++) {
            const int tk = stok[c][0];
            wxn[c] = __ldg(&g_EWx[tk * DD + eg]);
            ggn[c] = __ldg(&g_G[tk * DD + eg]);
        }
    }

    for (int t = 0; t < TT; t++) {
        const int buf = t & 3, nb = (t + 1) & 3;
        const int p = t & 1, np = p ^ 1;
        const bool last = (t == TT - 1);

        float wx[2] = {wxn[0], wxn[1]}, gg[2] = {ggn[0], ggn[1]};
        if (q == 0 && !last) {
#pragma unroll
            for (int c = 0; c < 2; c++) {
                const int tk = stok[c][t + 1];
                wxn[c] = __ldg(&g_EWx[tk * DD + eg]);
                ggn[c] = __ldg(&g_G[tk * DD + eg]);
            }
        }

#pragma unroll
        for (int c = 0; c < 2; c++) {
            // ---- phase A: local-half dot (barrier-ordered last step) ----
            unsigned long long aa = 0ull, ab = 0ull;
            {
                const ulonglong2* hb = (const ulonglong2*)(&hloc[c][p][36 * q]);
#pragma unroll
                for (int i = 0; i < 8; i++) {
                    ulonglong2 h2 = hb[i];
                    FFMA2(aa, wL[2 * i],     h2.x);
                    FFMA2(ab, wL[2 * i + 1], h2.y);
                }
            }
            const float sA = f32x2_hsum4(aa, ab);

            // ---- phase B: poll-by-computing on peer half (NaN gate) ----
            float sB;
            {
                const uint32_t pa = pbase[c] + buf * HB;
                unsigned long long hv0, hv1, ba, bb;
                while (true) {
                    ba = 0ull; bb = 0ull;
#pragma unroll
                    for (int i = 0; i < 8; i++) {
                        asm volatile("ld.volatile.shared.v2.u64 {%0, %1}, [%2];"
                                     : "=l"(hv0), "=l"(hv1) : "r"(pa + 16 * i));
                        FFMA2(ba, wR[2 * i],     hv0);
                        FFMA2(bb, wR[2 * i + 1], hv1);
                    }
                    sB = f32x2_hsum4(ba, bb);
                    if (!__isnanf(sB)) break;   // sentinel -> NaN -> retry
                }
            }

            float acc = sA + sB;
            acc += __shfl_xor_sync(0xffffffffu, acc, 1);
            acc += __shfl_xor_sync(0xffffffffu, acc, 2);

            if (q == 0) {
                const float hn = tanh_fast(acc + wx[c]);
                if (!last) {
                    // publish to peer ASAP (weak DSMEM store; value IS the flag)
                    asm volatile("st.shared::cluster.f32 [%0], %1;"
                                 :: "r"(rpub[c] + nb * HB), "f"(hn) : "memory");
                }
                hloc[c][np][jp] = hn;
                yb[c][(size_t)t * DD + eg] = hn * gg[c];
            }
        }

        __syncthreads();   // phase-B readers of buf done; hloc[np] visible

        // re-arm consumed buffers (next peer write lands >= 2 steps later,
        // causally ordered behind our own t+1/t+2 publishes)
        if (q == 1) {
            ((volatile unsigned int*)hrem[0][buf])[jp] = QNAN_U;
            ((volatile unsigned int*)hrem[1][buf])[jp] = QNAN_U;
        }
    }

    // exit safety: no CTA may leave while peer-directed traffic is in flight
    asm volatile("barrier.cluster.arrive.aligned;" ::: "memory");
    asm volatile("barrier.cluster.wait.aligned;"   ::: "memory");
}

// ================= Kernel 3: head GEMM =================
// logits[r][v] = sum_d y[r][d] * E[v][d].
// 64x64 tile per CTA, 4x4 micro-tile per thread, f32x2 pairs along k.
#define HKS 68   // 64 + 4 pad

__global__ __launch_bounds__(256) void head_kernel(
    const float* __restrict__ E,
    float* __restrict__ out)
{
    __shared__ __align__(16) float ys[64 * HKS];
    __shared__ __align__(16) float es[64 * HKS];

    const int tid = threadIdx.x;
    const int tx  = tid & 15;     // v-lane: cols tx, tx+16, tx+32, tx+48
    const int ty  = tid >> 4;     // row group: rows ty*4 .. ty*4+3
    const size_t rowbase = (size_t)(blockIdx.x >> 2) * 64;
    const int vbase = (blockIdx.x & 3) * 64;

    unsigned long long acc[4][4];
#pragma unroll
    for (int r = 0; r < 4; r++)
#pragma unroll
        for (int c = 0; c < 4; c++) acc[r][c] = 0ull;

    for (int kc = 0; kc < 4; kc++) {
        const int k0 = kc * 64;
        for (int i = tid; i < 1024; i += 256) {
            const int m = i >> 4, kk = i & 15;
            *(float4*)(ys + m * HKS + kk * 4) =
                *(const float4*)(g_y + (rowbase + m) * DD + k0 + kk * 4);
            *(float4*)(es + m * HKS + kk * 4) =
                *(const float4*)(E + (size_t)(vbase + m) * DD + k0 + kk * 4);
        }
        __syncthreads();

#pragma unroll
        for (int k4 = 0; k4 < 16; k4++) {
            ulonglong2 yv[4], ev[4];
#pragma unroll
            for (int r = 0; r < 4; r++)
                yv[r] = *(const ulonglong2*)(ys + (ty * 4 + r) * HKS + k4 * 4);
#pragma unroll
            for (int c = 0; c < 4; c++)
                ev[c] = *(const ulonglong2*)(es + (tx + 16 * c) * HKS + k4 * 4);
#pragma unroll
            for (int r = 0; r < 4; r++)
#pragma unroll
                for (int c = 0; c < 4; c++) {
                    FFMA2(acc[r][c], yv[r].x, ev[c].x);
                    FFMA2(acc[r][c], yv[r].y, ev[c].y);
                }
        }
        __syncthreads();
    }

#pragma unroll
    for (int r = 0; r < 4; r++) {
        float* orow = out + (rowbase + ty * 4 + r) * VV + vbase;
#pragma unroll
        for (int c = 0; c < 4; c++) {
            float lo, hi;
            asm("mov.b64 {%0, %1}, %2;" : "=f"(lo), "=f"(hi) : "l"(acc[r][c]));
            orow[tx + 16 * c] = lo + hi;
        }
    }
}

// ================= launch =================
extern "C" void kernel_launch(void* const* d_in, const int* in_sizes, int n_in,
                              void* d_out, int out_size)
{
    const int*   tokens = (const int*)  d_in[0];
    const float* E      = (const float*)d_in[1];
    const float* Wx     = (const float*)d_in[2];
    const float* Wh     = (const float*)d_in[3];
    const float* Wz     = (const float*)d_in[4];
    float* out = (float*)d_out;

    proj_kernel<<<VV, 256>>>(E, Wx, Wz);
    rnn_kernel<<<BB, 512>>>(tokens, Wh);
    head_kernel<<<(BB * TT / 64) * (VV / 64), 256>>>(E, out);
}

// round 9
// speedup vs baseline: 1.4694x; 1.4694x over previous
#include <cuda_runtime.h>
#include <cuda_bf16.h>
#include <cstdint>
#include <cstddef>

#define BB 64
#define TT 2048
#define DD 256
#define VV 256
#define QNAN_U 0x7fc00000u

// ---------------- device scratch (no cudaMalloc allowed) ----------------
__device__ __align__(16) float g_EWx[VV * DD];            // E @ Wx_w^T   [v][e]
__device__ __align__(16) float g_G[VV * DD];              // sigmoid(E @ Wz_w^T) [v][e]
__device__ __align__(16) float g_y[(size_t)BB * TT * DD]; // gated hidden states [b,t,e]

// ---------------- helpers ----------------
__device__ __forceinline__ uint32_t smem_u32(const void* p) {
    uint32_t a;
    asm("{ .reg .u64 t; cvta.to.shared.u64 t, %1; cvt.u32.u64 %0, t; }"
        : "=r"(a) : "l"(p));
    return a;
}

// packed fp32x2 FMA: acc = a*b + acc  (full fp32 precision, 2 MACs / instr)
#define FFMA2(acc, a, b) \
    asm("fma.rn.f32x2 %0, %1, %2, %0;" : "+l"(acc) : "l"(a), "l"(b))

__device__ __forceinline__ float f32x2_hsum4(unsigned long long a,
                                             unsigned long long b) {
    unsigned long long s;
    asm("add.rn.f32x2 %0, %1, %2;" : "=l"(s) : "l"(a), "l"(b));
    float lo, hi;
    asm("mov.b64 {%0, %1}, %2;" : "=f"(lo), "=f"(hi) : "l"(s));
    return lo + hi;
}

// fast tanh: 1 - 2/(exp(2x)+1); exact limits at +-inf, ~1e-6 rel err, never NaN
__device__ __forceinline__ float tanh_fast(float x) {
    float e = __expf(2.0f * x);
    return 1.0f - __fdividef(2.0f, e + 1.0f);
}

// ================= Kernel 1: tiny projection tables =================
__global__ __launch_bounds__(256) void proj_kernel(
    const float* __restrict__ E,
    const float* __restrict__ Wx,
    const float* __restrict__ Wz)
{
    __shared__ __align__(16) float4 er[DD / 4];
    const int v = blockIdx.x;
    const int e = threadIdx.x;
    if (e < DD / 4) er[e] = ((const float4*)(E + (size_t)v * DD))[e];
    __syncthreads();

    const float4* wx4 = (const float4*)(Wx + (size_t)e * DD);
    const float4* wz4 = (const float4*)(Wz + (size_t)e * DD);
    float ax0 = 0.f, ax1 = 0.f, az0 = 0.f, az1 = 0.f;
#pragma unroll 8
    for (int i = 0; i < DD / 4; i++) {
        float4 ev = er[i];
        float4 a = wx4[i];
        float4 b = wz4[i];
        ax0 += ev.x * a.x + ev.y * a.y;
        ax1 += ev.z * a.z + ev.w * a.w;
        az0 += ev.x * b.x + ev.y * b.y;
        az1 += ev.z * b.z + ev.w * b.w;
    }
    g_EWx[v * DD + e] = ax0 + ax1;
    g_G[v * DD + e]   = 1.f / (1.f + expf(-(az0 + az1)));
}

// ================= Kernel 2: recurrence (PARTIAL-SUM EXCHANGE) =================
// 2-CTA cluster per chain (128 clusters, 512 threads each). CTA rank r holds
// h-half r locally and NEVER needs the peer's h. Each thread (e = tid>>1 in
// [0,256), s = tid&1) computes the partial dot of output e over the CTA's
// LOCAL 128 k (slice 64s..64s+64 of the local half) -> all FMA is local-only.
//   - outputs e in the PEER's half: lane s==0 publishes the 128-k partial to
//     the peer's prem ring slot via weak st.shared::cluster (value-as-flag).
//   - outputs e in OUR half: lane s==0 polls the peer's partial (single float,
//     qNaN sentinel), adds own partial + wx, tanh, stores h locally + g_y.
// One __syncthreads per step; 4-deep ring; re-arm after the barrier (peer's
// next write to a slot is causally >= 3 steps behind the re-arm; CTA skew is
// self-limited to < 2 steps). Partials are finite always => NaN gate is safe.
#define SLOTW 132                 // 128 floats + 4 pad per ring slot
#define SLOTB (SLOTW * 4)

__global__ void __cluster_dims__(2, 1, 1) __launch_bounds__(512, 1)
rnn_kernel(const int* __restrict__ tokens, const float* __restrict__ Wh)
{
    __shared__ int stok[TT];
    __shared__ __align__(16) float hloc[2][128];     // local h half, 2 parities
    __shared__ __align__(16) float prem[4][SLOTW];   // peer partials ring

    const int tid  = threadIdx.x;
    const int bx   = blockIdx.x;
    const int b    = bx >> 1;
    const int rank = bx & 1;
    const int e    = tid >> 1;        // output index 0..255
    const int s    = tid & 1;         // k-subslice of local half
    const int el   = e & 127;
    const bool own = ((e >> 7) == rank);   // e in this CTA's output half?

    // ---- weights: Wh[e][128*rank + 64*s .. +64] as 32 f32x2 regs ----
    unsigned long long w[32];
    {
        const ulonglong2* ws = (const ulonglong2*)
            (Wh + (size_t)e * DD + 128 * rank + 64 * s);
#pragma unroll
        for (int j = 0; j < 16; j++) {
            ulonglong2 v = ws[j];
            w[2 * j] = v.x; w[2 * j + 1] = v.y;
        }
    }

    for (int i = tid; i < TT; i += 512) stok[i] = tokens[(size_t)b * TT + i];
    if (tid < 128) { hloc[0][tid] = 0.f; hloc[1][tid] = 0.f; }
    for (int i = tid; i < 4 * SLOTW; i += 512)
        ((unsigned int*)prem)[i] = QNAN_U;

    // cluster barrier: smem init visible before any peer traffic
    asm volatile("barrier.cluster.arrive.aligned;" ::: "memory");
    asm volatile("barrier.cluster.wait.aligned;"   ::: "memory");

    // publisher: remote address of peer's prem[0][el]
    uint32_t rpub = 0;
    if (!own && s == 0) {
        uint32_t la = smem_u32(&prem[0][el]);
        asm("mapa.shared::cluster.u32 %0, %1, %2;"
            : "=r"(rpub) : "r"(la), "r"(rank ^ 1));
    }
    // finalizer: local poll address of prem[0][el]
    const uint32_t pollA = smem_u32(&prem[0][el]);

    float* ybase = g_y + (size_t)b * TT * DD;

    // prefetch step-0 gathers (finalizer lanes only)
    float wxn = 0.f, ggn = 0.f;
    if (own && s == 0) {
        const int tk = stok[0];
        wxn = __ldg(&g_EWx[tk * DD + e]);
        ggn = __ldg(&g_G[tk * DD + e]);
    }

    int p = 0;
    for (int t = 0; t < TT; t++) {
        const int buf = t & 3;
        const float wx = wxn, gg = ggn;
        if (own && s == 0 && t + 1 < TT) {
            const int tk = stok[t + 1];
            wxn = __ldg(&g_EWx[tk * DD + e]);
            ggn = __ldg(&g_G[tk * DD + e]);
        }

        // ---- partial dot over LOCAL h half: 64 k per thread = 32 FFMA2 ----
        unsigned long long aa = 0ull, ab = 0ull;
        {
            const ulonglong2* hb = (const ulonglong2*)(&hloc[p][64 * s]);
#pragma unroll
            for (int i = 0; i < 16; i++) {
                ulonglong2 h2 = hb[i];
                FFMA2(aa, w[2 * i],     h2.x);
                FFMA2(ab, w[2 * i + 1], h2.y);
            }
        }
        float red = f32x2_hsum4(aa, ab);
        red += __shfl_xor_sync(0xffffffffu, red, 1);   // full 128-k partial

        const int np = p ^ 1;
        if (!own) {
            // publish partial for the peer's finalize of THIS step
            if (s == 0) {
                asm volatile("st.shared::cluster.f32 [%0], %1;"
                             :: "r"(rpub + buf * SLOTB), "f"(red) : "memory");
            }
        } else if (s == 0) {
            // poll the peer's partial for output e (value-as-flag)
            float pp;
            const uint32_t pa = pollA + buf * SLOTB;
            do {
                asm volatile("ld.volatile.shared.f32 %0, [%1];"
                             : "=f"(pp) : "r"(pa));
            } while (__isnanf(pp));
            const float hn = tanh_fast(red + pp + wx);
            hloc[np][el] = hn;
            ybase[(size_t)t * DD + e] = hn * gg;
        }

        __syncthreads();   // finalizers done: hloc[np] + slot consumption

        // re-arm the consumed slot (peer rewrites it >= 3 steps later,
        // causally behind our own t+1..t+3 publishes)
        if (tid < 128) ((volatile unsigned int*)prem[buf])[tid] = QNAN_U;
        p = np;
    }

    // exit safety: no CTA may leave while peer-directed traffic is in flight
    asm volatile("barrier.cluster.arrive.aligned;" ::: "memory");
    asm volatile("barrier.cluster.wait.aligned;"   ::: "memory");
}

// ================= Kernel 3: head GEMM =================
// logits[r][v] = sum_d y[r][d] * E[v][d].
// 64x64 tile per CTA, 4x4 micro-tile per thread, f32x2 pairs along k.
#define HKS 68   // 64 + 4 pad

__global__ __launch_bounds__(256) void head_kernel(
    const float* __restrict__ E,
    float* __restrict__ out)
{
    __shared__ __align__(16) float ys[64 * HKS];
    __shared__ __align__(16) float es[64 * HKS];

    const int tid = threadIdx.x;
    const int tx  = tid & 15;     // v-lane: cols tx, tx+16, tx+32, tx+48
    const int ty  = tid >> 4;     // row group: rows ty*4 .. ty*4+3
    const size_t rowbase = (size_t)(blockIdx.x >> 2) * 64;
    const int vbase = (blockIdx.x & 3) * 64;

    unsigned long long acc[4][4];
#pragma unroll
    for (int r = 0; r < 4; r++)
#pragma unroll
        for (int c = 0; c < 4; c++) acc[r][c] = 0ull;

    for (int kc = 0; kc < 4; kc++) {
        const int k0 = kc * 64;
        for (int i = tid; i < 1024; i += 256) {
            const int m = i >> 4, kk = i & 15;
            *(float4*)(ys + m * HKS + kk * 4) =
                *(const float4*)(g_y + (rowbase + m) * DD + k0 + kk * 4);
            *(float4*)(es + m * HKS + kk * 4) =
                *(const float4*)(E + (size_t)(vbase + m) * DD + k0 + kk * 4);
        }
        __syncthreads();

#pragma unroll
        for (int k4 = 0; k4 < 16; k4++) {
            ulonglong2 yv[4], ev[4];
#pragma unroll
            for (int r = 0; r < 4; r++)
                yv[r] = *(const ulonglong2*)(ys + (ty * 4 + r) * HKS + k4 * 4);
#pragma unroll
            for (int c = 0; c < 4; c++)
                ev[c] = *(const ulonglong2*)(es + (tx + 16 * c) * HKS + k4 * 4);
#pragma unroll
            for (int r = 0; r < 4; r++)
#pragma unroll
                for (int c = 0; c < 4; c++) {
                    FFMA2(acc[r][c], yv[r].x, ev[c].x);
                    FFMA2(acc[r][c], yv[r].y, ev[c].y);
                }
        }
        __syncthreads();
    }

#pragma unroll
    for (int r = 0; r < 4; r++) {
        float* orow = out + (rowbase + ty * 4 + r) * VV + vbase;
#pragma unroll
        for (int c = 0; c < 4; c++) {
            float lo, hi;
            asm("mov.b64 {%0, %1}, %2;" : "=f"(lo), "=f"(hi) : "l"(acc[r][c]));
            orow[tx + 16 * c] = lo + hi;
        }
    }
}

// ================= launch =================
extern "C" void kernel_launch(void* const* d_in, const int* in_sizes, int n_in,
                              void* d_out, int out_size)
{
    const int*   tokens = (const int*)  d_in[0];
    const float* E      = (const float*)d_in[1];
    const float* Wx     = (const float*)d_in[2];
    const float* Wh     = (const float*)d_in[3];
    const float* Wz     = (const float*)d_in[4];
    float* out = (float*)d_out;

    proj_kernel<<<VV, 256>>>(E, Wx, Wz);
    rnn_kernel<<<BB * 2, 512>>>(tokens, Wh);
    head_kernel<<<(BB * TT / 64) * (VV / 64), 256>>>(E, out);
}

// round 10
// speedup vs baseline: 1.5113x; 1.0286x over previous
#include <cuda_runtime.h>
#include <cuda_bf16.h>
#include <cstdint>
#include <cstddef>

#define BB 64
#define TT 2048
#define DD 256
#define VV 256
#define QNAN_U 0x7fc00000u

// ---------------- device scratch (no cudaMalloc allowed) ----------------
__device__ __align__(16) float g_EWx[VV * DD];            // E @ Wx_w^T   [v][e]
__device__ __align__(16) float g_G[VV * DD];              // sigmoid(E @ Wz_w^T) [v][e]
__device__ __align__(16) float g_y[(size_t)BB * TT * DD]; // gated hidden states [b,t,e]

// ---------------- helpers ----------------
__device__ __forceinline__ uint32_t smem_u32(const void* p) {
    uint32_t a;
    asm("{ .reg .u64 t; cvta.to.shared.u64 t, %1; cvt.u32.u64 %0, t; }"
        : "=r"(a) : "l"(p));
    return a;
}

// packed fp32x2 FMA: acc = a*b + acc  (full fp32 precision, 2 MACs / instr)
#define FFMA2(acc, a, b) \
    asm("fma.rn.f32x2 %0, %1, %2, %0;" : "+l"(acc) : "l"(a), "l"(b))

__device__ __forceinline__ float f32x2_hsum4(unsigned long long a,
                                             unsigned long long b) {
    unsigned long long s;
    asm("add.rn.f32x2 %0, %1, %2;" : "=l"(s) : "l"(a), "l"(b));
    float lo, hi;
    asm("mov.b64 {%0, %1}, %2;" : "=f"(lo), "=f"(hi) : "l"(s));
    return lo + hi;
}

// fast tanh: 1 - 2/(exp(2x)+1); exact limits at +-inf, ~1e-6 rel err, never NaN
__device__ __forceinline__ float tanh_fast(float x) {
    float e = __expf(2.0f * x);
    return 1.0f - __fdividef(2.0f, e + 1.0f);
}

// ================= Kernel 1: tiny projection tables =================
__global__ __launch_bounds__(256) void proj_kernel(
    const float* __restrict__ E,
    const float* __restrict__ Wx,
    const float* __restrict__ Wz)
{
    __shared__ __align__(16) float4 er[DD / 4];
    const int v = blockIdx.x;
    const int e = threadIdx.x;
    if (e < DD / 4) er[e] = ((const float4*)(E + (size_t)v * DD))[e];
    __syncthreads();

    const float4* wx4 = (const float4*)(Wx + (size_t)e * DD);
    const float4* wz4 = (const float4*)(Wz + (size_t)e * DD);
    float ax0 = 0.f, ax1 = 0.f, az0 = 0.f, az1 = 0.f;
#pragma unroll 8
    for (int i = 0; i < DD / 4; i++) {
        float4 ev = er[i];
        float4 a = wx4[i];
        float4 b = wz4[i];
        ax0 += ev.x * a.x + ev.y * a.y;
        ax1 += ev.z * a.z + ev.w * a.w;
        az0 += ev.x * b.x + ev.y * b.y;
        az1 += ev.z * b.z + ev.w * b.w;
    }
    g_EWx[v * DD + e] = ax0 + ax1;
    g_G[v * DD + e]   = 1.f / (1.f + expf(-(az0 + az1)));
}

// ============ Kernel 2: recurrence (PARTIAL-SUM EXCHANGE, PULL) ============
// 2-CTA cluster per chain (128 clusters, 512 threads each). CTA rank r holds
// h-half r locally; all FMA uses only local h. Thread (e = tid>>1, s = tid&1)
// computes the 64-k sub-dot of output e over the CTA's local 128 k.
// TRANSPORT = PULL (this round's variable under test):
//   - publishers (e in peer's half, s==0) store the 128-k partial into an
//     EXPORT ring in their OWN smem (strong relaxed local store, instantly
//     visible to incoming remote loads), and re-arm slot (t+2)&3 to qNaN
//     (same-thread same-address ordering; peer consumed it >= 2 steps ago by
//     the skew<2 causality bound).
//   - finalizers (own outputs, s==0) REMOTE-LOAD the peer's export slot via
//     ld.relaxed.cluster (measured ~215 cyc path), polling the qNaN sentinel,
//     then add own partial + wx, tanh, store h locally + g_y.
// No remote stores, no fences, no mbarriers; one __syncthreads per step.
#define SLOTW 132                 // 128 floats + 4 pad per ring slot
#define SLOTB (SLOTW * 4)

__global__ void __cluster_dims__(2, 1, 1) __launch_bounds__(512, 1)
rnn_kernel(const int* __restrict__ tokens, const float* __restrict__ Wh)
{
    __shared__ int stok[TT];
    __shared__ __align__(16) float hloc[2][128];     // local h half, 2 parities
    __shared__ __align__(16) float pexp[4][SLOTW];   // EXPORT ring (peer pulls)

    const int tid  = threadIdx.x;
    const int bx   = blockIdx.x;
    const int b    = bx >> 1;
    const int rank = bx & 1;
    const int e    = tid >> 1;        // output index 0..255
    const int s    = tid & 1;         // k-subslice of local half
    const int el   = e & 127;
    const bool own = ((e >> 7) == rank);   // e in this CTA's output half?

    // ---- weights: Wh[e][128*rank + 64*s .. +64] as 32 f32x2 regs ----
    unsigned long long w[32];
    {
        const ulonglong2* ws = (const ulonglong2*)
            (Wh + (size_t)e * DD + 128 * rank + 64 * s);
#pragma unroll
        for (int j = 0; j < 16; j++) {
            ulonglong2 v = ws[j];
            w[2 * j] = v.x; w[2 * j + 1] = v.y;
        }
    }

    for (int i = tid; i < TT; i += 512) stok[i] = tokens[(size_t)b * TT + i];
    if (tid < 128) { hloc[0][tid] = 0.f; hloc[1][tid] = 0.f; }
    for (int i = tid; i < 4 * SLOTW; i += 512)
        ((unsigned int*)pexp)[i] = QNAN_U;

    // cluster barrier: smem init visible before any peer traffic
    asm volatile("barrier.cluster.arrive.aligned;" ::: "memory");
    asm volatile("barrier.cluster.wait.aligned;"   ::: "memory");

    // publisher: LOCAL export address for output el
    const uint32_t expA = smem_u32(&pexp[0][el]);
    // finalizer: REMOTE poll address = peer's pexp[0][el]
    uint32_t rpoll = 0;
    if (own && s == 0) {
        asm("mapa.shared::cluster.u32 %0, %1, %2;"
            : "=r"(rpoll) : "r"(expA), "r"(rank ^ 1));
    }

    float* ybase = g_y + (size_t)b * TT * DD;

    // prefetch step-0 gathers (finalizer lanes only)
    float wxn = 0.f, ggn = 0.f;
    if (own && s == 0) {
        const int tk = stok[0];
        wxn = __ldg(&g_EWx[tk * DD + e]);
        ggn = __ldg(&g_G[tk * DD + e]);
    }

    int p = 0;
    for (int t = 0; t < TT; t++) {
        const int buf = t & 3;
        const float wx = wxn, gg = ggn;
        if (own && s == 0 && t + 1 < TT) {
            const int tk = stok[t + 1];
            wxn = __ldg(&g_EWx[tk * DD + e]);
            ggn = __ldg(&g_G[tk * DD + e]);
        }

        // ---- partial dot over LOCAL h half: 64 k per thread = 32 FFMA2 ----
        unsigned long long aa = 0ull, ab = 0ull;
        {
            const ulonglong2* hb = (const ulonglong2*)(&hloc[p][64 * s]);
#pragma unroll
            for (int i = 0; i < 16; i++) {
                ulonglong2 h2 = hb[i];
                FFMA2(aa, w[2 * i],     h2.x);
                FFMA2(ab, w[2 * i + 1], h2.y);
            }
        }
        float red = f32x2_hsum4(aa, ab);
        red += __shfl_xor_sync(0xffffffffu, red, 1);   // full 128-k partial

        const int np = p ^ 1;
        if (!own) {
            if (s == 0) {
                // export partial LOCALLY for the peer to pull (strong relaxed)
                asm volatile("st.relaxed.cluster.shared::cta.f32 [%0], %1;"
                             :: "r"(expA + buf * SLOTB), "f"(red) : "memory");
                // re-arm slot (t+2)&3: peer consumed it >= 2 steps ago
                asm volatile("st.relaxed.cluster.shared::cta.b32 [%0], %1;"
                             :: "r"(expA + (((t + 2) & 3) * SLOTB)),
                                "r"(QNAN_U) : "memory");
            }
        } else if (s == 0) {
            // pull the peer's partial for output e (value-as-flag, ~215cyc RTT)
            float pp;
            const uint32_t pa = rpoll + buf * SLOTB;
            do {
                asm volatile("ld.relaxed.cluster.shared::cluster.f32 %0, [%1];"
                             : "=f"(pp) : "r"(pa) : "memory");
            } while (__isnanf(pp));
            const float hn = tanh_fast(red + pp + wx);
            hloc[np][el] = hn;
            ybase[(size_t)t * DD + e] = hn * gg;
        }

        __syncthreads();   // hloc[np] visible CTA-wide for next step
        p = np;
    }

    // exit safety: peer may still be remote-READING our smem; hold until both done
    asm volatile("barrier.cluster.arrive.aligned;" ::: "memory");
    asm volatile("barrier.cluster.wait.aligned;"   ::: "memory");
}

// ================= Kernel 3: head GEMM =================
// logits[r][v] = sum_d y[r][d] * E[v][d].
// 64x64 tile per CTA, 4x4 micro-tile per thread, f32x2 pairs along k.
#define HKS 68   // 64 + 4 pad

__global__ __launch_bounds__(256) void head_kernel(
    const float* __restrict__ E,
    float* __restrict__ out)
{
    __shared__ __align__(16) float ys[64 * HKS];
    __shared__ __align__(16) float es[64 * HKS];

    const int tid = threadIdx.x;
    const int tx  = tid & 15;     // v-lane: cols tx, tx+16, tx+32, tx+48
    const int ty  = tid >> 4;     // row group: rows ty*4 .. ty*4+3
    const size_t rowbase = (size_t)(blockIdx.x >> 2) * 64;
    const int vbase = (blockIdx.x & 3) * 64;

    unsigned long long acc[4][4];
#pragma unroll
    for (int r = 0; r < 4; r++)
#pragma unroll
        for (int c = 0; c < 4; c++) acc[r][c] = 0ull;

    for (int kc = 0; kc < 4; kc++) {
        const int k0 = kc * 64;
        for (int i = tid; i < 1024; i += 256) {
            const int m = i >> 4, kk = i & 15;
            *(float4*)(ys + m * HKS + kk * 4) =
                *(const float4*)(g_y + (rowbase + m) * DD + k0 + kk * 4);
            *(float4*)(es + m * HKS + kk * 4) =
                *(const float4*)(E + (size_t)(vbase + m) * DD + k0 + kk * 4);
        }
        __syncthreads();

#pragma unroll
        for (int k4 = 0; k4 < 16; k4++) {
            ulonglong2 yv[4], ev[4];
#pragma unroll
            for (int r = 0; r < 4; r++)
                yv[r] = *(const ulonglong2*)(ys + (ty * 4 + r) * HKS + k4 * 4);
#pragma unroll
            for (int c = 0; c < 4; c++)
                ev[c] = *(const ulonglong2*)(es + (tx + 16 * c) * HKS + k4 * 4);
#pragma unroll
            for (int r = 0; r < 4; r++)
#pragma unroll
                for (int c = 0; c < 4; c++) {
                    FFMA2(acc[r][c], yv[r].x, ev[c].x);
                    FFMA2(acc[r][c], yv[r].y, ev[c].y);
                }
        }
        __syncthreads();
    }

#pragma unroll
    for (int r = 0; r < 4; r++) {
        float* orow = out + (rowbase + ty * 4 + r) * VV + vbase;
#pragma unroll
        for (int c = 0; c < 4; c++) {
            float lo, hi;
            asm("mov.b64 {%0, %1}, %2;" : "=f"(lo), "=f"(hi) : "l"(acc[r][c]));
            orow[tx + 16 * c] = lo + hi;
        }
    }
}

// ================= launch =================
extern "C" void kernel_launch(void* const* d_in, const int* in_sizes, int n_in,
                              void* d_out, int out_size)
{
    const int*   tokens = (const int*)  d_in[0];
    const float* E      = (const float*)d_in[1];
    const float* Wx     = (const float*)d_in[2];
    const float* Wh     = (const float*)d_in[3];
    const float* Wz     = (const float*)d_in[4];
    float* out = (float*)d_out;

    proj_kernel<<<VV, 256>>>(E, Wx, Wz);
    rnn_kernel<<<BB * 2, 512>>>(tokens, Wh);
    head_kernel<<<(BB * TT / 64) * (VV / 64), 256>>>(E, out);
}